// round 16
// baseline (speedup 1.0000x reference)
#include <cuda_runtime.h>

// Problem constants
#define LAYERS 12
#define BATCH  16
#define HEADS  12
#define N      197
#define KSEL   98            // int(197 * 0.5)

#define HALF0  99            // rows [0, 99) -> half 0
#define TPH    224           // threads per half (7 warps)
#define TPB    448           // threads per block (14 warps)

// ---------------------------------------------------------------------------
// Kernel 0: paint output with the "unselected" one-hot (1, 0).
// ---------------------------------------------------------------------------
__global__ void init_out_kernel(float* __restrict__ out) {
    int t = blockIdx.x * blockDim.x + threadIdx.x;   // over BATCH*N
    if (t < BATCH * N) {
        out[2 * t + 0] = 1.0f;
        out[2 * t + 1] = 0.0f;
    }
}

// ---------------------------------------------------------------------------
// Kernel 1: one CTA per (modality, b, h), 448 threads, 2-way dot-split.
//   Single barrier per layer: halves write partials into separate ping-pong
//   arrays p0/p1; v[i] = p0[i]+p1[i] formed on the fly (same FP order as
//   the 2-barrier version). Next layer's first 16-load batch is prefetched
//   into registers BEFORE the barrier so DRAM streams through the sync.
// ---------------------------------------------------------------------------
__global__ __launch_bounds__(TPB, 3)
void chain_select_kernel(const float* __restrict__ rgb,
                         const float* __restrict__ tir,
                         float* __restrict__ out) {
    const int bid = blockIdx.x;                 // [0, 2*BATCH*HEADS)
    const int mod = bid / (BATCH * HEADS);
    const int bh  = bid % (BATCH * HEADS);
    const int b   = bh / HEADS;

    const float* base = (mod == 0) ? rgb : tir;
    const size_t mat  = (size_t)N * N;

    __shared__ float p0[2][N];      // half-0 partials, ping-pong
    __shared__ float p1[2][N];      // half-1 partials, ping-pong
    __shared__ float sc[N];         // final combined vector

    const int tid  = threadIdx.x;
    const int half = tid / TPH;     // 0 or 1
    const int j    = tid % TPH;     // column owned (active if j < N)
    const int ilo  = half ? HALF0 : 0;
    const int ihi  = half ? N     : HALF0;

    // Layer-10 base (first matrix consumed by the chain loop).
    const float* A = base + ((size_t)10 * BATCH * HEADS + (size_t)bh) * mat;

    // Init: v = row 0 of A[11]; stored split as p0 = row, p1 = 0.
    {
        const float* a11 = base + ((size_t)11 * BATCH * HEADS + (size_t)bh) * mat;
        if (tid < N) { p0[0][tid] = __ldcs(&a11[tid]); p1[0][tid] = 0.0f; }
    }

    // Prefetch layer-10 batch 0 (rows ilo..ilo+15 of column j).
    float pa[16];
    if (j < N) {
        const float* col = A + j;
        #pragma unroll
        for (int k = 0; k < 16; ++k)
            pa[k] = __ldcs(&col[(size_t)(ilo + k) * N]);
    }
    __syncthreads();

    int cur = 0;
    for (int l = 10; l >= 0; --l) {
        const float* __restrict__ c0 = p0[cur];
        const float* __restrict__ c1 = p1[cur];

        float acc = 0.0f;
        if (j < N) {
            const float* col = A + j;
            // Batch 0: consume the prefetched registers (data landed during
            // the previous barrier drain).
            #pragma unroll
            for (int k = 0; k < 16; ++k)
                acc += (c0[ilo + k] + c1[ilo + k]) * pa[k];

            int i = ilo + 16;
            // Remaining batches: 16 front-batched LDGs, then FMAs.
            #pragma unroll 1
            for (; i + 16 <= ihi; i += 16) {
                float a0  = __ldcs(&col[(size_t)(i +  0) * N]);
                float a1  = __ldcs(&col[(size_t)(i +  1) * N]);
                float a2  = __ldcs(&col[(size_t)(i +  2) * N]);
                float a3  = __ldcs(&col[(size_t)(i +  3) * N]);
                float a4  = __ldcs(&col[(size_t)(i +  4) * N]);
                float a5  = __ldcs(&col[(size_t)(i +  5) * N]);
                float a6  = __ldcs(&col[(size_t)(i +  6) * N]);
                float a7  = __ldcs(&col[(size_t)(i +  7) * N]);
                float a8  = __ldcs(&col[(size_t)(i +  8) * N]);
                float a9  = __ldcs(&col[(size_t)(i +  9) * N]);
                float a10 = __ldcs(&col[(size_t)(i + 10) * N]);
                float a11 = __ldcs(&col[(size_t)(i + 11) * N]);
                float a12 = __ldcs(&col[(size_t)(i + 12) * N]);
                float a13 = __ldcs(&col[(size_t)(i + 13) * N]);
                float a14 = __ldcs(&col[(size_t)(i + 14) * N]);
                float a15 = __ldcs(&col[(size_t)(i + 15) * N]);
                acc += (c0[i +  0] + c1[i +  0]) * a0;
                acc += (c0[i +  1] + c1[i +  1]) * a1;
                acc += (c0[i +  2] + c1[i +  2]) * a2;
                acc += (c0[i +  3] + c1[i +  3]) * a3;
                acc += (c0[i +  4] + c1[i +  4]) * a4;
                acc += (c0[i +  5] + c1[i +  5]) * a5;
                acc += (c0[i +  6] + c1[i +  6]) * a6;
                acc += (c0[i +  7] + c1[i +  7]) * a7;
                acc += (c0[i +  8] + c1[i +  8]) * a8;
                acc += (c0[i +  9] + c1[i +  9]) * a9;
                acc += (c0[i + 10] + c1[i + 10]) * a10;
                acc += (c0[i + 11] + c1[i + 11]) * a11;
                acc += (c0[i + 12] + c1[i + 12]) * a12;
                acc += (c0[i + 13] + c1[i + 13]) * a13;
                acc += (c0[i + 14] + c1[i + 14]) * a14;
                acc += (c0[i + 15] + c1[i + 15]) * a15;
            }
            for (; i < ihi; ++i)
                acc += (c0[i] + c1[i]) * __ldcs(&col[(size_t)i * N]);
        }

        // Prefetch NEXT layer's batch 0 before the barrier: these loads are
        // independent of v, so they stream during the barrier drain.
        if (l > 0) {
            A = base + ((size_t)(l - 1) * BATCH * HEADS + (size_t)bh) * mat;
            if (j < N) {
                const float* col = A + j;
                #pragma unroll
                for (int k = 0; k < 16; ++k)
                    pa[k] = __ldcs(&col[(size_t)(ilo + k) * N]);
            }
        }

        // Publish partial; each half fully covers j in [0, N).
        if (j < N) {
            if (half) p1[1 - cur][j] = acc;
            else      p0[1 - cur][j] = acc;
        }
        __syncthreads();            // single barrier per layer
        cur = 1 - cur;
    }

    // Combine final vector once for the rank loop.
    if (tid < N) sc[tid] = p0[cur][tid] + p1[cur][tid];
    __syncthreads();

    // Stable top-K on scores s[t] = sc[t+1], t in [0, N-1):
    // rank(t) = #{ i : s[i] > s[t] or (s[i] == s[t] and i < t) }; select
    // iff rank < KSEL. Matches lax.top_k tie order.
    if (half == 0 && j < N - 1) {
        const float sj = sc[j + 1];
        int cnt = 0;
        #pragma unroll 4
        for (int i = 0; i < N - 1; ++i) {
            const float si = sc[i + 1];
            cnt += (si > sj) || (si == sj && i < j);
        }
        if (cnt < KSEL) {
            // Selected: (0,1) one-hot; identical value from every writer.
            float2* o = (float2*)(out + 2 * (b * N + j));
            *o = make_float2(0.0f, 1.0f);
        }
    }
    // Mask slot N-1 (=196) is never set: the reference writes top-k indices
    // of the 196-long score vector directly into the 197-long mask.
}

// ---------------------------------------------------------------------------
extern "C" void kernel_launch(void* const* d_in, const int* in_sizes, int n_in,
                              void* d_out, int out_size) {
    const float* rgb = (const float*)d_in[0];
    const float* tir = (const float*)d_in[1];
    float* out = (float*)d_out;

    (void)in_sizes; (void)n_in; (void)out_size;

    const int flags = BATCH * N;

    init_out_kernel<<<(flags + 255) / 256, 256>>>(out);
    chain_select_kernel<<<2 * BATCH * HEADS, TPB>>>(rgb, tir, out);
}